// round 5
// baseline (speedup 1.0000x reference)
#include <cuda_runtime.h>
#include <math.h>

// ---------------------------------------------------------------------------
// AttentionModule: B=2, N=M=F=1024, E=64, G=16, dg=64, DIM_OUT=1024 (O=64/g)
//
// out[b,n,g,o] = sum_m softmax_m( log(max(relu(pe[b,n,m,:]·pos_w[g]+pos_b[g]),eps))
//                                 + (q[b,n,g,:]·k[b,m,g,:])/8 ) * V[b,m,g,o] + conv_b
// with q = roi@q_w^T + q_b, k = roi@k_w^T + k_b, V = roi@conv_w^T   (projection
// commuted through the attention sum: exact, saves 16x FLOPs on the PV stage)
// ---------------------------------------------------------------------------

// scratch (device globals: allocation-free per harness rules)
__device__ float g_q[2u * 1024u * 1024u];          // [b][n][g*64+d]
__device__ float g_k[2u * 1024u * 1024u];          // [b][m][g*64+d]
__device__ float g_v[2u * 1024u * 1024u];          // [b][m][g*64+o]
__device__ float g_p[32u * 1024u * 1024u];         // [b*16+g][n][m]  (aff -> p in place)

// ---------------------------------------------------------------------------
// Kernel 1: projection GEMM  C(2048 x 3072) = roi(2048 x 1024) @ W^T
// 128x128x16 tiles, 256 threads, 8x8 per thread.
// ---------------------------------------------------------------------------
__global__ __launch_bounds__(256)
void proj_kernel(const float* __restrict__ A,
                 const float* __restrict__ qw, const float* __restrict__ qb,
                 const float* __restrict__ kw, const float* __restrict__ kb,
                 const float* __restrict__ cw)
{
    __shared__ float As[16][128];
    __shared__ float Bs[16][128];
    const int tid  = threadIdx.x;
    const int row0 = blockIdx.y * 128;
    const int j0   = blockIdx.x * 128;
    const int which = j0 >> 10;       // 0: q, 1: k, 2: v
    const int jj0   = j0 & 1023;
    const float* __restrict__ W = (which == 0) ? qw : ((which == 1) ? kw : cw);
    float* Out = (which == 0) ? g_q : ((which == 1) ? g_k : g_v);
    const float* bias = (which == 0) ? qb : ((which == 1) ? kb : nullptr);

    const int lr  = tid >> 2;         // 0..63 loader row
    const int lc  = (tid & 3) << 2;   // 0,4,8,12 loader col (k)
    const int tm0 = (tid >> 4) << 3;  // 0..120 output row base
    const int tn0 = (tid & 15) << 3;  // 0..120 output col base

    float acc[8][8];
#pragma unroll
    for (int i = 0; i < 8; i++)
#pragma unroll
        for (int j = 0; j < 8; j++) acc[i][j] = 0.f;

    for (int kt = 0; kt < 1024; kt += 16) {
        float4 a0 = *(const float4*)(A + (size_t)(row0 + lr) * 1024 + kt + lc);
        float4 a1 = *(const float4*)(A + (size_t)(row0 + lr + 64) * 1024 + kt + lc);
        float4 b0 = *(const float4*)(W + (size_t)(jj0 + lr) * 1024 + kt + lc);
        float4 b1 = *(const float4*)(W + (size_t)(jj0 + lr + 64) * 1024 + kt + lc);
        __syncthreads();
        As[lc + 0][lr] = a0.x; As[lc + 1][lr] = a0.y; As[lc + 2][lr] = a0.z; As[lc + 3][lr] = a0.w;
        As[lc + 0][lr + 64] = a1.x; As[lc + 1][lr + 64] = a1.y; As[lc + 2][lr + 64] = a1.z; As[lc + 3][lr + 64] = a1.w;
        Bs[lc + 0][lr] = b0.x; Bs[lc + 1][lr] = b0.y; Bs[lc + 2][lr] = b0.z; Bs[lc + 3][lr] = b0.w;
        Bs[lc + 0][lr + 64] = b1.x; Bs[lc + 1][lr + 64] = b1.y; Bs[lc + 2][lr + 64] = b1.z; Bs[lc + 3][lr + 64] = b1.w;
        __syncthreads();
#pragma unroll
        for (int k = 0; k < 16; k++) {
            float4 am0 = *(const float4*)&As[k][tm0];
            float4 am1 = *(const float4*)&As[k][tm0 + 4];
            float4 bn0 = *(const float4*)&Bs[k][tn0];
            float4 bn1 = *(const float4*)&Bs[k][tn0 + 4];
            float ar[8] = {am0.x, am0.y, am0.z, am0.w, am1.x, am1.y, am1.z, am1.w};
            float br[8] = {bn0.x, bn0.y, bn0.z, bn0.w, bn1.x, bn1.y, bn1.z, bn1.w};
#pragma unroll
            for (int i = 0; i < 8; i++)
#pragma unroll
                for (int j = 0; j < 8; j++) acc[i][j] += ar[i] * br[j];
        }
    }

    float bv[8];
#pragma unroll
    for (int j = 0; j < 8; j++) bv[j] = bias ? bias[jj0 + tn0 + j] : 0.f;
#pragma unroll
    for (int i = 0; i < 8; i++) {
        const int r = row0 + tm0 + i;
        float4 o0, o1;
        o0.x = acc[i][0] + bv[0]; o0.y = acc[i][1] + bv[1];
        o0.z = acc[i][2] + bv[2]; o0.w = acc[i][3] + bv[3];
        o1.x = acc[i][4] + bv[4]; o1.y = acc[i][5] + bv[5];
        o1.z = acc[i][6] + bv[6]; o1.w = acc[i][7] + bv[7];
        *(float4*)(Out + (size_t)r * 1024 + jj0 + tn0)     = o0;
        *(float4*)(Out + (size_t)r * 1024 + jj0 + tn0 + 4) = o1;
    }
}

// ---------------------------------------------------------------------------
// Kernel 2: aff[b,g,n,m] = 0.125 * sum_d q[b,n,g,d]*k[b,m,g,d]
// Batched over (b,g): 32 batches of (1024 x 1024 x 64). 128x128 tile.
// ---------------------------------------------------------------------------
__global__ __launch_bounds__(256)
void aff_kernel()
{
    __shared__ float Qs[32][132];
    __shared__ float Ks[32][132];
    const int tid = threadIdx.x;
    const int b = blockIdx.z >> 4;
    const int g = blockIdx.z & 15;
    const int n0 = blockIdx.y << 7;
    const int m0 = blockIdx.x << 7;
    const float* __restrict__ qp = g_q + (size_t)b * 1048576 + g * 64;
    const float* __restrict__ kp = g_k + (size_t)b * 1048576 + g * 64;

    const int lrow = tid >> 3;          // 0..31
    const int ld   = (tid & 7) << 2;    // 0..28
    const int tn0  = (tid >> 4) << 3;
    const int tm0  = (tid & 15) << 3;

    float acc[8][8];
#pragma unroll
    for (int i = 0; i < 8; i++)
#pragma unroll
        for (int j = 0; j < 8; j++) acc[i][j] = 0.f;

    for (int kt = 0; kt < 64; kt += 32) {
        __syncthreads();
#pragma unroll
        for (int it = 0; it < 4; it++) {
            const int rr = lrow + it * 32;
            float4 qv = *(const float4*)(qp + (size_t)(n0 + rr) * 1024 + kt + ld);
            float4 kv = *(const float4*)(kp + (size_t)(m0 + rr) * 1024 + kt + ld);
            Qs[ld + 0][rr] = qv.x; Qs[ld + 1][rr] = qv.y; Qs[ld + 2][rr] = qv.z; Qs[ld + 3][rr] = qv.w;
            Ks[ld + 0][rr] = kv.x; Ks[ld + 1][rr] = kv.y; Ks[ld + 2][rr] = kv.z; Ks[ld + 3][rr] = kv.w;
        }
        __syncthreads();
#pragma unroll
        for (int d = 0; d < 32; d++) {
            float4 a0 = *(const float4*)&Qs[d][tn0];
            float4 a1 = *(const float4*)&Qs[d][tn0 + 4];
            float4 c0 = *(const float4*)&Ks[d][tm0];
            float4 c1 = *(const float4*)&Ks[d][tm0 + 4];
            float ar[8] = {a0.x, a0.y, a0.z, a0.w, a1.x, a1.y, a1.z, a1.w};
            float br[8] = {c0.x, c0.y, c0.z, c0.w, c1.x, c1.y, c1.z, c1.w};
#pragma unroll
            for (int i = 0; i < 8; i++)
#pragma unroll
                for (int j = 0; j < 8; j++) acc[i][j] += ar[i] * br[j];
        }
    }

    float* op = g_p + (size_t)(b * 16 + g) * 1048576;
#pragma unroll
    for (int i = 0; i < 8; i++) {
        const int nr = n0 + tn0 + i;
        float4 o0, o1;
        o0.x = acc[i][0] * 0.125f; o0.y = acc[i][1] * 0.125f;
        o0.z = acc[i][2] * 0.125f; o0.w = acc[i][3] * 0.125f;
        o1.x = acc[i][4] * 0.125f; o1.y = acc[i][5] * 0.125f;
        o1.z = acc[i][6] * 0.125f; o1.w = acc[i][7] * 0.125f;
        *(float4*)(op + (size_t)nr * 1024 + m0 + tm0)     = o0;
        *(float4*)(op + (size_t)nr * 1024 + m0 + tm0 + 4) = o1;
    }
}

// ---------------------------------------------------------------------------
// Kernel 3: p = softmax_m( log(max(relu(pe·pos_w^T+pos_b),eps)) + aff ), in
// place over g_p. One block of 256 threads per (b,n). Logits for all 16
// groups x 1024 m live in DYNAMIC SHARED MEMORY (64 KB) — zero per-thread
// local arrays, so the local-memory pool never grows (the allocation guard
// counts any local pool growth as an allocation).
//   smem layout (floats): [0,1024) pos_w, [1024,1040) pos_b,
//                         [1056, 1056+16*1024) logits[g][m]
// ---------------------------------------------------------------------------
__global__ __launch_bounds__(256, 2)
void softmax_kernel(const float* __restrict__ pe,
                    const float* __restrict__ pos_w,
                    const float* __restrict__ pos_b)
{
    extern __shared__ float sm[];
    float* pwS   = sm;            // 1024
    float* pbS   = sm + 1024;     // 16
    float* logit = sm + 1056;     // 16*1024

    const int tid = threadIdx.x;
    const int n = blockIdx.x;
    const int b = blockIdx.y;

    for (int i = tid; i < 1024; i += 256) pwS[i] = pos_w[i];
    if (tid < 16) pbS[tid] = pos_b[tid];
    __syncthreads();

    const float4* pw4 = (const float4*)pwS;   // pw4[g*16+c] = pos_w[g][4c..4c+3]
    const size_t pe_base = ((size_t)b * 1024 + n) * 65536;
    const size_t aff_row = (size_t)(b * 16) * 1048576 + (size_t)n * 1024;

    // Phase 1: pos-embedding dot + log + aff -> logits in smem
#pragma unroll
    for (int i = 0; i < 4; i++) {
        const int m = tid + (i << 8);
        const float4* p4 = (const float4*)(pe + pe_base + (size_t)m * 64);
        float s[16];
#pragma unroll
        for (int g = 0; g < 16; g++) s[g] = pbS[g];
#pragma unroll
        for (int c = 0; c < 16; c++) {
            const float4 e = p4[c];
#pragma unroll
            for (int g = 0; g < 16; g++) {
                const float4 wv = pw4[g * 16 + c];
                s[g] += e.x * wv.x + e.y * wv.y + e.z * wv.z + e.w * wv.w;
            }
        }
#pragma unroll
        for (int g = 0; g < 16; g++) {
            float x = (s[g] > 1e-6f) ? __logf(s[g]) : -13.815510557964274f;
            x += g_p[aff_row + (size_t)g * 1048576 + m];
            logit[g * 1024 + m] = x;
        }
    }
    __syncthreads();

    // Phase 2: per-group softmax. Warp w handles groups 2w and 2w+1.
    const int lane = tid & 31;
    const int wrp  = tid >> 5;   // 0..7
#pragma unroll
    for (int gi = 0; gi < 2; gi++) {
        const int g = wrp * 2 + gi;
        const float* lg = logit + g * 1024;
        float l[32];
        float mx = -1e30f;
#pragma unroll
        for (int k = 0; k < 32; k++) {
            l[k] = lg[lane + (k << 5)];
            mx = fmaxf(mx, l[k]);
        }
#pragma unroll
        for (int o = 16; o > 0; o >>= 1) mx = fmaxf(mx, __shfl_xor_sync(0xffffffffu, mx, o));
        float t = 0.f;
#pragma unroll
        for (int k = 0; k < 32; k++) { l[k] = __expf(l[k] - mx); t += l[k]; }
#pragma unroll
        for (int o = 16; o > 0; o >>= 1) t += __shfl_xor_sync(0xffffffffu, t, o);
        const float inv = 1.f / t;
        float* pr = g_p + aff_row + (size_t)g * 1048576;
#pragma unroll
        for (int k = 0; k < 32; k++) pr[lane + (k << 5)] = l[k] * inv;
    }
}

// ---------------------------------------------------------------------------
// Kernel 4: out[b,n,g*64+o] = sum_m p[b,g,n,m] * V[b,m,g*64+o] + conv_b
// Batched (b,g): 32 x (1024n x 64o x 1024m). Tile 128n x 64o, K tile 32.
// ---------------------------------------------------------------------------
__global__ __launch_bounds__(256)
void out_kernel(float* __restrict__ out, const float* __restrict__ cb)
{
    __shared__ float Ps[32][132];
    __shared__ float Vs[32][68];
    const int tid = threadIdx.x;
    const int bg = blockIdx.y;
    const int b = bg >> 4;
    const int g = bg & 15;
    const int n0 = blockIdx.x << 7;
    const float* __restrict__ pp = g_p + (size_t)bg * 1048576;
    const float* __restrict__ vp = g_v + (size_t)b * 1048576 + g * 64;

    const int plr = tid >> 3;          // p loader row 0..31
    const int plc = (tid & 7) << 2;    // p loader m 0..28
    const int vlr = tid >> 4;          // v loader m 0..15
    const int vlc = (tid & 15) << 2;   // v loader o 0..60
    const int tn0 = (tid >> 3) << 2;   // out n base 0..124
    const int to0 = (tid & 7) << 3;    // out o base 0..56

    float acc[4][8];
#pragma unroll
    for (int i = 0; i < 4; i++)
#pragma unroll
        for (int j = 0; j < 8; j++) acc[i][j] = 0.f;

    for (int mt = 0; mt < 1024; mt += 32) {
        __syncthreads();
#pragma unroll
        for (int it = 0; it < 4; it++) {
            const int nr = plr + it * 32;
            float4 pv = *(const float4*)(pp + (size_t)(n0 + nr) * 1024 + mt + plc);
            Ps[plc + 0][nr] = pv.x; Ps[plc + 1][nr] = pv.y;
            Ps[plc + 2][nr] = pv.z; Ps[plc + 3][nr] = pv.w;
        }
#pragma unroll
        for (int it = 0; it < 2; it++) {
            const int mr = vlr + it * 16;
            float4 vv = *(const float4*)(vp + (size_t)(mt + mr) * 1024 + vlc);
            *(float4*)&Vs[mr][vlc] = vv;
        }
        __syncthreads();
#pragma unroll
        for (int m = 0; m < 32; m++) {
            float4 a  = *(const float4*)&Ps[m][tn0];
            float4 v0 = *(const float4*)&Vs[m][to0];
            float4 v1 = *(const float4*)&Vs[m][to0 + 4];
            float ar[4] = {a.x, a.y, a.z, a.w};
            float vr[8] = {v0.x, v0.y, v0.z, v0.w, v1.x, v1.y, v1.z, v1.w};
#pragma unroll
            for (int i = 0; i < 4; i++)
#pragma unroll
                for (int j = 0; j < 8; j++) acc[i][j] += ar[i] * vr[j];
        }
    }

    float bv[8];
#pragma unroll
    for (int j = 0; j < 8; j++) bv[j] = cb[g * 64 + to0 + j];
#pragma unroll
    for (int i = 0; i < 4; i++) {
        const int nr = n0 + tn0 + i;
        float4 o0, o1;
        o0.x = acc[i][0] + bv[0]; o0.y = acc[i][1] + bv[1];
        o0.z = acc[i][2] + bv[2]; o0.w = acc[i][3] + bv[3];
        o1.x = acc[i][4] + bv[4]; o1.y = acc[i][5] + bv[5];
        o1.z = acc[i][6] + bv[6]; o1.w = acc[i][7] + bv[7];
        *(float4*)(out + ((size_t)(b * 1024 + nr)) * 1024 + g * 64 + to0)     = o0;
        *(float4*)(out + ((size_t)(b * 1024 + nr)) * 1024 + g * 64 + to0 + 4) = o1;
    }
}

static const int kSoftmaxSmem = (1056 + 16 * 1024) * 4;   // 69,760 bytes

// ---------------------------------------------------------------------------
extern "C" void kernel_launch(void* const* d_in, const int* in_sizes, int n_in,
                              void* d_out, int out_size)
{
    (void)in_sizes; (void)n_in; (void)out_size;
    const float* roi   = (const float*)d_in[0];
    const float* pe    = (const float*)d_in[1];
    const float* pos_w = (const float*)d_in[2];
    const float* pos_b = (const float*)d_in[3];
    const float* q_w   = (const float*)d_in[4];
    const float* q_b   = (const float*)d_in[5];
    const float* k_w   = (const float*)d_in[6];
    const float* k_b   = (const float*)d_in[7];
    const float* c_w   = (const float*)d_in[8];
    const float* c_b   = (const float*)d_in[9];
    float* out = (float*)d_out;

    // idempotent, deterministic, not a stream op -> graph-capture safe
    cudaFuncSetAttribute(softmax_kernel,
                         cudaFuncAttributeMaxDynamicSharedMemorySize, kSoftmaxSmem);

    proj_kernel<<<dim3(24, 16), 256>>>(roi, q_w, q_b, k_w, k_b, c_w);
    aff_kernel<<<dim3(8, 8, 32), 256>>>();
    softmax_kernel<<<dim3(1024, 2), 256, kSoftmaxSmem>>>(pe, pos_w, pos_b);
    out_kernel<<<dim3(8, 32), 256>>>(out, c_b);
}

// round 10
// speedup vs baseline: 1.0986x; 1.0986x over previous
#include <cuda_runtime.h>
#include <math.h>
#include <cstdint>

// ---------------------------------------------------------------------------
// AttentionModule: B=2, N=M=F=1024, E=64, G=16, dg=64, DIM_OUT=1024 (O=64/g)
// out[b,n,g,o] = sum_m softmax_m( log(max(relu(pe·pos_w[g]+pos_b[g]),eps))
//                                 + (q·k)/8 ) * V[b,m,g,o] + conv_b
// q/k/V projections commuted through the attention sum (16x FLOP saving on PV).
// This round: proj GEMM on tensor cores via mma.sync tf32 (arch-portable PTX;
// tcgen05 is unavailable because the harness compiles PTX for compute_103,
// not compute_103a).
// ---------------------------------------------------------------------------

// scratch (device globals: allocation-free per harness rules)
__device__ float g_q[2u * 1024u * 1024u];          // [b][n][g*64+d]
__device__ float g_k[2u * 1024u * 1024u];          // [b][m][g*64+d]
__device__ float g_v[2u * 1024u * 1024u];          // [b][m][g*64+o]
__device__ float g_p[32u * 1024u * 1024u];         // [b*16+g][n][m]

__device__ __forceinline__ uint32_t f2tf32(float x) {
    uint32_t u;
    asm("cvt.rna.tf32.f32 %0, %1;" : "=r"(u) : "f"(x));
    return u;
}
__device__ __forceinline__ void mma_tf32(float* c, const uint32_t* a, const uint32_t* b) {
    asm volatile(
        "mma.sync.aligned.m16n8k8.row.col.f32.tf32.tf32.f32 "
        "{%0,%1,%2,%3}, {%4,%5,%6,%7}, {%8,%9}, {%0,%1,%2,%3};"
        : "+f"(c[0]), "+f"(c[1]), "+f"(c[2]), "+f"(c[3])
        : "r"(a[0]), "r"(a[1]), "r"(a[2]), "r"(a[3]), "r"(b[0]), "r"(b[1]));
}

// ---------------------------------------------------------------------------
// Kernel 1 (tensor core, tf32): C(2048 x 3072) = roi(2048x1024) @ W^T
// W in {q_w,k_w,conv_w} by column block; writes g_q/g_k/g_v (+bias).
// 128x128 block tile, 8 warps (2x4), warp tile 64x32, K-chunk 32.
// m16n8k8 fragments loaded from tf32-converted smem (stride 36: conflict-free).
// ---------------------------------------------------------------------------
__global__ __launch_bounds__(256, 2)
void proj_mma_kernel(const float* __restrict__ A,
                     const float* __restrict__ qw, const float* __restrict__ qb,
                     const float* __restrict__ kw, const float* __restrict__ kb,
                     const float* __restrict__ cw)
{
    __shared__ uint32_t As[128][36];
    __shared__ uint32_t Bs[128][36];

    const int tid  = threadIdx.x;
    const int wid  = tid >> 5;
    const int lane = tid & 31;
    const int row0 = blockIdx.y * 128;
    const int j0   = blockIdx.x * 128;
    const int which = j0 >> 10;       // 0: q, 1: k, 2: v
    const int jj0   = j0 & 1023;
    const float* __restrict__ W = (which == 0) ? qw : ((which == 1) ? kw : cw);
    float* Out = (which == 0) ? g_q : ((which == 1) ? g_k : g_v);
    const float* bias = (which == 0) ? qb : ((which == 1) ? kb : nullptr);

    const int wm = (wid >> 2) * 64;   // warp m offset: 0 / 64
    const int wn = (wid & 3) * 32;    // warp n offset: 0/32/64/96
    const int qrow = lane >> 2;       // 0..7
    const int qcol = lane & 3;        // 0..3

    const int lrow = tid >> 3;        // loader row 0..31
    const int lcol = (tid & 7) << 2;  // loader k 0,4,..,28

    float acc[4][4][4];
#pragma unroll
    for (int mi = 0; mi < 4; mi++)
#pragma unroll
        for (int ni = 0; ni < 4; ni++)
#pragma unroll
            for (int r = 0; r < 4; r++) acc[mi][ni][r] = 0.f;

    for (int kt = 0; kt < 1024; kt += 32) {
        const float* Ag = A + (size_t)row0 * 1024 + kt;
        const float* Bg = W + (size_t)jj0 * 1024 + kt;
        __syncthreads();
#pragma unroll
        for (int it = 0; it < 4; it++) {
            const int r = lrow + it * 32;
            float4 va = *(const float4*)(Ag + (size_t)r * 1024 + lcol);
            float4 vb = *(const float4*)(Bg + (size_t)r * 1024 + lcol);
            As[r][lcol + 0] = f2tf32(va.x); As[r][lcol + 1] = f2tf32(va.y);
            As[r][lcol + 2] = f2tf32(va.z); As[r][lcol + 3] = f2tf32(va.w);
            Bs[r][lcol + 0] = f2tf32(vb.x); Bs[r][lcol + 1] = f2tf32(vb.y);
            Bs[r][lcol + 2] = f2tf32(vb.z); Bs[r][lcol + 3] = f2tf32(vb.w);
        }
        __syncthreads();
#pragma unroll
        for (int ks = 0; ks < 4; ks++) {
            const int kk = ks * 8;
            uint32_t af[4][4];
#pragma unroll
            for (int mi = 0; mi < 4; mi++) {
                const int r = wm + mi * 16;
                af[mi][0] = As[r + qrow][kk + qcol];
                af[mi][1] = As[r + 8 + qrow][kk + qcol];
                af[mi][2] = As[r + qrow][kk + 4 + qcol];
                af[mi][3] = As[r + 8 + qrow][kk + 4 + qcol];
            }
            uint32_t bf[4][2];
#pragma unroll
            for (int ni = 0; ni < 4; ni++) {
                const int c = wn + ni * 8;
                bf[ni][0] = Bs[c + qrow][kk + qcol];
                bf[ni][1] = Bs[c + qrow][kk + 4 + qcol];
            }
#pragma unroll
            for (int mi = 0; mi < 4; mi++)
#pragma unroll
                for (int ni = 0; ni < 4; ni++)
                    mma_tf32(acc[mi][ni], af[mi], bf[ni]);
        }
    }

    // epilogue: c0/c1 -> row lane/4, cols 2*(lane&3)+{0,1}; c2/c3 -> row+8
#pragma unroll
    for (int mi = 0; mi < 4; mi++) {
        const int r = row0 + wm + mi * 16 + qrow;
#pragma unroll
        for (int ni = 0; ni < 4; ni++) {
            const int c = jj0 + wn + ni * 8 + qcol * 2;
            float b0 = bias ? bias[c] : 0.f;
            float b1 = bias ? bias[c + 1] : 0.f;
            float2 o0, o1;
            o0.x = acc[mi][ni][0] + b0; o0.y = acc[mi][ni][1] + b1;
            o1.x = acc[mi][ni][2] + b0; o1.y = acc[mi][ni][3] + b1;
            *(float2*)(Out + (size_t)r * 1024 + c)       = o0;
            *(float2*)(Out + (size_t)(r + 8) * 1024 + c) = o1;
        }
    }
}

// ---------------------------------------------------------------------------
// Kernel 2: aff[b,g,n,m] = 0.125 * sum_d q[b,n,g,d]*k[b,m,g,d]   (fp32 SIMT)
// ---------------------------------------------------------------------------
__global__ __launch_bounds__(256)
void aff_kernel()
{
    __shared__ float Qs[32][132];
    __shared__ float Ks[32][132];
    const int tid = threadIdx.x;
    const int b = blockIdx.z >> 4;
    const int g = blockIdx.z & 15;
    const int n0 = blockIdx.y << 7;
    const int m0 = blockIdx.x << 7;
    const float* __restrict__ qp = g_q + (size_t)b * 1048576 + g * 64;
    const float* __restrict__ kp = g_k + (size_t)b * 1048576 + g * 64;

    const int lrow = tid >> 3;
    const int ld   = (tid & 7) << 2;
    const int tn0  = (tid >> 4) << 3;
    const int tm0  = (tid & 15) << 3;

    float acc[8][8];
#pragma unroll
    for (int i = 0; i < 8; i++)
#pragma unroll
        for (int j = 0; j < 8; j++) acc[i][j] = 0.f;

    for (int kt = 0; kt < 64; kt += 32) {
        __syncthreads();
#pragma unroll
        for (int it = 0; it < 4; it++) {
            const int rr = lrow + it * 32;
            float4 qv = *(const float4*)(qp + (size_t)(n0 + rr) * 1024 + kt + ld);
            float4 kv = *(const float4*)(kp + (size_t)(m0 + rr) * 1024 + kt + ld);
            Qs[ld + 0][rr] = qv.x; Qs[ld + 1][rr] = qv.y; Qs[ld + 2][rr] = qv.z; Qs[ld + 3][rr] = qv.w;
            Ks[ld + 0][rr] = kv.x; Ks[ld + 1][rr] = kv.y; Ks[ld + 2][rr] = kv.z; Ks[ld + 3][rr] = kv.w;
        }
        __syncthreads();
#pragma unroll
        for (int d = 0; d < 32; d++) {
            float4 a0 = *(const float4*)&Qs[d][tn0];
            float4 a1 = *(const float4*)&Qs[d][tn0 + 4];
            float4 c0 = *(const float4*)&Ks[d][tm0];
            float4 c1 = *(const float4*)&Ks[d][tm0 + 4];
            float ar[8] = {a0.x, a0.y, a0.z, a0.w, a1.x, a1.y, a1.z, a1.w};
            float br[8] = {c0.x, c0.y, c0.z, c0.w, c1.x, c1.y, c1.z, c1.w};
#pragma unroll
            for (int i = 0; i < 8; i++)
#pragma unroll
                for (int j = 0; j < 8; j++) acc[i][j] += ar[i] * br[j];
        }
    }

    float* op = g_p + (size_t)(b * 16 + g) * 1048576;
#pragma unroll
    for (int i = 0; i < 8; i++) {
        const int nr = n0 + tn0 + i;
        float4 o0, o1;
        o0.x = acc[i][0] * 0.125f; o0.y = acc[i][1] * 0.125f;
        o0.z = acc[i][2] * 0.125f; o0.w = acc[i][3] * 0.125f;
        o1.x = acc[i][4] * 0.125f; o1.y = acc[i][5] * 0.125f;
        o1.z = acc[i][6] * 0.125f; o1.w = acc[i][7] * 0.125f;
        *(float4*)(op + (size_t)nr * 1024 + m0 + tm0)     = o0;
        *(float4*)(op + (size_t)nr * 1024 + m0 + tm0 + 4) = o1;
    }
}

// ---------------------------------------------------------------------------
// Kernel 3: p = softmax_m( log(max(relu(pe·pos_w^T+pos_b),eps)) + aff )
// Logits in dynamic smem (no per-thread local arrays -> local pool stays 0).
// ---------------------------------------------------------------------------
__global__ __launch_bounds__(256, 2)
void softmax_kernel(const float* __restrict__ pe,
                    const float* __restrict__ pos_w,
                    const float* __restrict__ pos_b)
{
    extern __shared__ float sm[];
    float* pwS   = sm;            // 1024
    float* pbS   = sm + 1024;     // 16
    float* logit = sm + 1056;     // 16*1024

    const int tid = threadIdx.x;
    const int n = blockIdx.x;
    const int b = blockIdx.y;

    for (int i = tid; i < 1024; i += 256) pwS[i] = pos_w[i];
    if (tid < 16) pbS[tid] = pos_b[tid];
    __syncthreads();

    const float4* pw4 = (const float4*)pwS;
    const size_t pe_base = ((size_t)b * 1024 + n) * 65536;
    const size_t aff_row = (size_t)(b * 16) * 1048576 + (size_t)n * 1024;

#pragma unroll
    for (int i = 0; i < 4; i++) {
        const int m = tid + (i << 8);
        const float4* p4 = (const float4*)(pe + pe_base + (size_t)m * 64);
        float s[16];
#pragma unroll
        for (int g = 0; g < 16; g++) s[g] = pbS[g];
#pragma unroll
        for (int c = 0; c < 16; c++) {
            const float4 e = p4[c];
#pragma unroll
            for (int g = 0; g < 16; g++) {
                const float4 wv = pw4[g * 16 + c];
                s[g] += e.x * wv.x + e.y * wv.y + e.z * wv.z + e.w * wv.w;
            }
        }
#pragma unroll
        for (int g = 0; g < 16; g++) {
            float x = (s[g] > 1e-6f) ? __logf(s[g]) : -13.815510557964274f;
            x += g_p[aff_row + (size_t)g * 1048576 + m];
            logit[g * 1024 + m] = x;
        }
    }
    __syncthreads();

    const int lane = tid & 31;
    const int wrp  = tid >> 5;
#pragma unroll
    for (int gi = 0; gi < 2; gi++) {
        const int g = wrp * 2 + gi;
        const float* lg = logit + g * 1024;
        float l[32];
        float mx = -1e30f;
#pragma unroll
        for (int k = 0; k < 32; k++) {
            l[k] = lg[lane + (k << 5)];
            mx = fmaxf(mx, l[k]);
        }
#pragma unroll
        for (int o = 16; o > 0; o >>= 1) mx = fmaxf(mx, __shfl_xor_sync(0xffffffffu, mx, o));
        float t = 0.f;
#pragma unroll
        for (int k = 0; k < 32; k++) { l[k] = __expf(l[k] - mx); t += l[k]; }
#pragma unroll
        for (int o = 16; o > 0; o >>= 1) t += __shfl_xor_sync(0xffffffffu, t, o);
        const float inv = 1.f / t;
        float* pr = g_p + aff_row + (size_t)g * 1048576;
#pragma unroll
        for (int k = 0; k < 32; k++) pr[lane + (k << 5)] = l[k] * inv;
    }
}

// ---------------------------------------------------------------------------
// Kernel 4: out[b,n,g*64+o] = sum_m p[b,g,n,m] * V[b,m,g*64+o] + conv_b
// ---------------------------------------------------------------------------
__global__ __launch_bounds__(256)
void out_kernel(float* __restrict__ out, const float* __restrict__ cb)
{
    __shared__ float Ps[32][132];
    __shared__ float Vs[32][68];
    const int tid = threadIdx.x;
    const int bg = blockIdx.y;
    const int b = bg >> 4;
    const int g = bg & 15;
    const int n0 = blockIdx.x << 7;
    const float* __restrict__ pp = g_p + (size_t)bg * 1048576;
    const float* __restrict__ vp = g_v + (size_t)b * 1048576 + g * 64;

    const int plr = tid >> 3;
    const int plc = (tid & 7) << 2;
    const int vlr = tid >> 4;
    const int vlc = (tid & 15) << 2;
    const int tn0 = (tid >> 3) << 2;
    const int to0 = (tid & 7) << 3;

    float acc[4][8];
#pragma unroll
    for (int i = 0; i < 4; i++)
#pragma unroll
        for (int j = 0; j < 8; j++) acc[i][j] = 0.f;

    for (int mt = 0; mt < 1024; mt += 32) {
        __syncthreads();
#pragma unroll
        for (int it = 0; it < 4; it++) {
            const int nr = plr + it * 32;
            float4 pv = *(const float4*)(pp + (size_t)(n0 + nr) * 1024 + mt + plc);
            Ps[plc + 0][nr] = pv.x; Ps[plc + 1][nr] = pv.y;
            Ps[plc + 2][nr] = pv.z; Ps[plc + 3][nr] = pv.w;
        }
#pragma unroll
        for (int it = 0; it < 2; it++) {
            const int mr = vlr + it * 16;
            float4 vv = *(const float4*)(vp + (size_t)(mt + mr) * 1024 + vlc);
            *(float4*)&Vs[mr][vlc] = vv;
        }
        __syncthreads();
#pragma unroll
        for (int m = 0; m < 32; m++) {
            float4 a  = *(const float4*)&Ps[m][tn0];
            float4 v0 = *(const float4*)&Vs[m][to0];
            float4 v1 = *(const float4*)&Vs[m][to0 + 4];
            float ar[4] = {a.x, a.y, a.z, a.w};
            float vr[8] = {v0.x, v0.y, v0.z, v0.w, v1.x, v1.y, v1.z, v1.w};
#pragma unroll
            for (int i = 0; i < 4; i++)
#pragma unroll
                for (int j = 0; j < 8; j++) acc[i][j] += ar[i] * vr[j];
        }
    }

    float bv[8];
#pragma unroll
    for (int j = 0; j < 8; j++) bv[j] = cb[g * 64 + to0 + j];
#pragma unroll
    for (int i = 0; i < 4; i++) {
        const int nr = n0 + tn0 + i;
        float4 o0, o1;
        o0.x = acc[i][0] + bv[0]; o0.y = acc[i][1] + bv[1];
        o0.z = acc[i][2] + bv[2]; o0.w = acc[i][3] + bv[3];
        o1.x = acc[i][4] + bv[4]; o1.y = acc[i][5] + bv[5];
        o1.z = acc[i][6] + bv[6]; o1.w = acc[i][7] + bv[7];
        *(float4*)(out + ((size_t)(b * 1024 + nr)) * 1024 + g * 64 + to0)     = o0;
        *(float4*)(out + ((size_t)(b * 1024 + nr)) * 1024 + g * 64 + to0 + 4) = o1;
    }
}

static const int kSoftmaxSmem = (1056 + 16 * 1024) * 4;   // 69,760 bytes

// ---------------------------------------------------------------------------
extern "C" void kernel_launch(void* const* d_in, const int* in_sizes, int n_in,
                              void* d_out, int out_size)
{
    (void)in_sizes; (void)n_in; (void)out_size;
    const float* roi   = (const float*)d_in[0];
    const float* pe    = (const float*)d_in[1];
    const float* pos_w = (const float*)d_in[2];
    const float* pos_b = (const float*)d_in[3];
    const float* q_w   = (const float*)d_in[4];
    const float* q_b   = (const float*)d_in[5];
    const float* k_w   = (const float*)d_in[6];
    const float* k_b   = (const float*)d_in[7];
    const float* c_w   = (const float*)d_in[8];
    const float* c_b   = (const float*)d_in[9];
    float* out = (float*)d_out;

    cudaFuncSetAttribute(softmax_kernel,
                         cudaFuncAttributeMaxDynamicSharedMemorySize, kSoftmaxSmem);

    proj_mma_kernel<<<dim3(24, 16), 256>>>(roi, q_w, q_b, k_w, k_b, c_w);
    aff_kernel<<<dim3(8, 8, 32), 256>>>();
    softmax_kernel<<<dim3(1024, 2), 256, kSoftmaxSmem>>>(pe, pos_w, pos_b);
    out_kernel<<<dim3(8, 32), 256>>>(out, c_b);
}

// round 14
// speedup vs baseline: 1.2074x; 1.0991x over previous
#include <cuda_runtime.h>
#include <math.h>
#include <cstdint>

// ---------------------------------------------------------------------------
// AttentionModule: B=2, N=M=F=1024, E=64, G=16, dg=64, DIM_OUT=1024 (O=64/g)
// out[b,n,g,o] = sum_m softmax_m( log(max(relu(pe·pos_w[g]+pos_b[g]),eps))
//                                 + (q·k)/8 ) * V[b,m,g,o] + conv_b
// q/k/V projections commuted through the attention sum (16x FLOP saving on PV).
// proj, aff and out GEMMs on tensor cores via mma.sync tf32 (arch-portable
// PTX; tcgen05 unavailable: harness compiles PTX for compute_103, not _103a).
// ---------------------------------------------------------------------------

// scratch (device globals: allocation-free per harness rules)
__device__ float g_q[2u * 1024u * 1024u];          // [b][n][g*64+d]
__device__ float g_k[2u * 1024u * 1024u];          // [b][m][g*64+d]
__device__ float g_v[2u * 1024u * 1024u];          // [b][m][g*64+o]
__device__ float g_p[32u * 1024u * 1024u];         // [b*16+g][n][m]

__device__ __forceinline__ uint32_t f2tf32(float x) {
    uint32_t u;
    asm("cvt.rna.tf32.f32 %0, %1;" : "=r"(u) : "f"(x));
    return u;
}
__device__ __forceinline__ void mma_tf32(float* c, const uint32_t* a, const uint32_t* b) {
    asm volatile(
        "mma.sync.aligned.m16n8k8.row.col.f32.tf32.tf32.f32 "
        "{%0,%1,%2,%3}, {%4,%5,%6,%7}, {%8,%9}, {%0,%1,%2,%3};"
        : "+f"(c[0]), "+f"(c[1]), "+f"(c[2]), "+f"(c[3])
        : "r"(a[0]), "r"(a[1]), "r"(a[2]), "r"(a[3]), "r"(b[0]), "r"(b[1]));
}

// ---------------------------------------------------------------------------
// Kernel 1 (tf32 mma): C(2048 x 3072) = roi(2048x1024) @ W^T
// 128x128 block tile, 8 warps (2x4), warp tile 64x32, K-chunk 32.
// ---------------------------------------------------------------------------
__global__ __launch_bounds__(256, 2)
void proj_mma_kernel(const float* __restrict__ A,
                     const float* __restrict__ qw, const float* __restrict__ qb,
                     const float* __restrict__ kw, const float* __restrict__ kb,
                     const float* __restrict__ cw)
{
    __shared__ uint32_t As[128][36];
    __shared__ uint32_t Bs[128][36];

    const int tid  = threadIdx.x;
    const int wid  = tid >> 5;
    const int lane = tid & 31;
    const int row0 = blockIdx.y * 128;
    const int j0   = blockIdx.x * 128;
    const int which = j0 >> 10;       // 0: q, 1: k, 2: v
    const int jj0   = j0 & 1023;
    const float* __restrict__ W = (which == 0) ? qw : ((which == 1) ? kw : cw);
    float* Out = (which == 0) ? g_q : ((which == 1) ? g_k : g_v);
    const float* bias = (which == 0) ? qb : ((which == 1) ? kb : nullptr);

    const int wm = (wid >> 2) * 64;
    const int wn = (wid & 3) * 32;
    const int qrow = lane >> 2;
    const int qcol = lane & 3;
    const int lrow = tid >> 3;
    const int lcol = (tid & 7) << 2;

    float acc[4][4][4];
#pragma unroll
    for (int mi = 0; mi < 4; mi++)
#pragma unroll
        for (int ni = 0; ni < 4; ni++)
#pragma unroll
            for (int r = 0; r < 4; r++) acc[mi][ni][r] = 0.f;

    for (int kt = 0; kt < 1024; kt += 32) {
        const float* Ag = A + (size_t)row0 * 1024 + kt;
        const float* Bg = W + (size_t)jj0 * 1024 + kt;
        __syncthreads();
#pragma unroll
        for (int it = 0; it < 4; it++) {
            const int r = lrow + it * 32;
            float4 va = *(const float4*)(Ag + (size_t)r * 1024 + lcol);
            float4 vb = *(const float4*)(Bg + (size_t)r * 1024 + lcol);
            As[r][lcol + 0] = f2tf32(va.x); As[r][lcol + 1] = f2tf32(va.y);
            As[r][lcol + 2] = f2tf32(va.z); As[r][lcol + 3] = f2tf32(va.w);
            Bs[r][lcol + 0] = f2tf32(vb.x); Bs[r][lcol + 1] = f2tf32(vb.y);
            Bs[r][lcol + 2] = f2tf32(vb.z); Bs[r][lcol + 3] = f2tf32(vb.w);
        }
        __syncthreads();
#pragma unroll
        for (int ks = 0; ks < 4; ks++) {
            const int kk = ks * 8;
            uint32_t af[4][4];
#pragma unroll
            for (int mi = 0; mi < 4; mi++) {
                const int r = wm + mi * 16;
                af[mi][0] = As[r + qrow][kk + qcol];
                af[mi][1] = As[r + 8 + qrow][kk + qcol];
                af[mi][2] = As[r + qrow][kk + 4 + qcol];
                af[mi][3] = As[r + 8 + qrow][kk + 4 + qcol];
            }
            uint32_t bf[4][2];
#pragma unroll
            for (int ni = 0; ni < 4; ni++) {
                const int c = wn + ni * 8;
                bf[ni][0] = Bs[c + qrow][kk + qcol];
                bf[ni][1] = Bs[c + qrow][kk + 4 + qcol];
            }
#pragma unroll
            for (int mi = 0; mi < 4; mi++)
#pragma unroll
                for (int ni = 0; ni < 4; ni++)
                    mma_tf32(acc[mi][ni], af[mi], bf[ni]);
        }
    }

#pragma unroll
    for (int mi = 0; mi < 4; mi++) {
        const int r = row0 + wm + mi * 16 + qrow;
#pragma unroll
        for (int ni = 0; ni < 4; ni++) {
            const int c = jj0 + wn + ni * 8 + qcol * 2;
            float b0 = bias ? bias[c] : 0.f;
            float b1 = bias ? bias[c + 1] : 0.f;
            float2 o0, o1;
            o0.x = acc[mi][ni][0] + b0; o0.y = acc[mi][ni][1] + b1;
            o1.x = acc[mi][ni][2] + b0; o1.y = acc[mi][ni][3] + b1;
            *(float2*)(Out + (size_t)r * 1024 + c)       = o0;
            *(float2*)(Out + (size_t)(r + 8) * 1024 + c) = o1;
        }
    }
}

// ---------------------------------------------------------------------------
// Kernel 2 (tf32 mma): aff[b,g,n,m] = 0.125 * q[b,n,g,:]·k[b,m,g,:]
// Per (b,g): C(1024n x 1024m) = q(1024x64) @ k(1024x64)^T. Same tile plan as
// proj: 128x128 block, warp 64x32, K = 64 in two 32-chunks.
// ---------------------------------------------------------------------------
__global__ __launch_bounds__(256, 2)
void aff_mma_kernel()
{
    __shared__ uint32_t Qs[128][36];
    __shared__ uint32_t Ks[128][36];

    const int tid  = threadIdx.x;
    const int wid  = tid >> 5;
    const int lane = tid & 31;
    const int b  = blockIdx.z >> 4;
    const int g  = blockIdx.z & 15;
    const int n0 = blockIdx.y << 7;
    const int m0 = blockIdx.x << 7;
    const float* __restrict__ qp = g_q + (size_t)b * 1048576 + g * 64;
    const float* __restrict__ kp = g_k + (size_t)b * 1048576 + g * 64;

    const int wm = (wid >> 2) * 64;   // n offset in tile
    const int wn = (wid & 3) * 32;    // m offset in tile
    const int qrow = lane >> 2;
    const int qcol = lane & 3;
    const int lrow = tid >> 3;
    const int lcol = (tid & 7) << 2;

    float acc[4][4][4];
#pragma unroll
    for (int mi = 0; mi < 4; mi++)
#pragma unroll
        for (int ni = 0; ni < 4; ni++)
#pragma unroll
            for (int r = 0; r < 4; r++) acc[mi][ni][r] = 0.f;

#pragma unroll
    for (int kt = 0; kt < 64; kt += 32) {
        __syncthreads();
#pragma unroll
        for (int it = 0; it < 4; it++) {
            const int r = lrow + it * 32;
            float4 qv = *(const float4*)(qp + (size_t)(n0 + r) * 1024 + kt + lcol);
            float4 kv = *(const float4*)(kp + (size_t)(m0 + r) * 1024 + kt + lcol);
            Qs[r][lcol + 0] = f2tf32(qv.x); Qs[r][lcol + 1] = f2tf32(qv.y);
            Qs[r][lcol + 2] = f2tf32(qv.z); Qs[r][lcol + 3] = f2tf32(qv.w);
            Ks[r][lcol + 0] = f2tf32(kv.x); Ks[r][lcol + 1] = f2tf32(kv.y);
            Ks[r][lcol + 2] = f2tf32(kv.z); Ks[r][lcol + 3] = f2tf32(kv.w);
        }
        __syncthreads();
#pragma unroll
        for (int ks = 0; ks < 4; ks++) {
            const int kk = ks * 8;
            uint32_t af[4][4];
#pragma unroll
            for (int mi = 0; mi < 4; mi++) {
                const int r = wm + mi * 16;
                af[mi][0] = Qs[r + qrow][kk + qcol];
                af[mi][1] = Qs[r + 8 + qrow][kk + qcol];
                af[mi][2] = Qs[r + qrow][kk + 4 + qcol];
                af[mi][3] = Qs[r + 8 + qrow][kk + 4 + qcol];
            }
            uint32_t bf[4][2];
#pragma unroll
            for (int ni = 0; ni < 4; ni++) {
                const int c = wn + ni * 8;
                bf[ni][0] = Ks[c + qrow][kk + qcol];
                bf[ni][1] = Ks[c + qrow][kk + 4 + qcol];
            }
#pragma unroll
            for (int mi = 0; mi < 4; mi++)
#pragma unroll
                for (int ni = 0; ni < 4; ni++)
                    mma_tf32(acc[mi][ni], af[mi], bf[ni]);
        }
    }

    float* op = g_p + (size_t)(b * 16 + g) * 1048576;
#pragma unroll
    for (int mi = 0; mi < 4; mi++) {
        const int r = n0 + wm + mi * 16 + qrow;
#pragma unroll
        for (int ni = 0; ni < 4; ni++) {
            const int c = m0 + wn + ni * 8 + qcol * 2;
            float2 o0, o1;
            o0.x = acc[mi][ni][0] * 0.125f; o0.y = acc[mi][ni][1] * 0.125f;
            o1.x = acc[mi][ni][2] * 0.125f; o1.y = acc[mi][ni][3] * 0.125f;
            *(float2*)(op + (size_t)r * 1024 + c)       = o0;
            *(float2*)(op + (size_t)(r + 8) * 1024 + c) = o1;
        }
    }
}

// ---------------------------------------------------------------------------
// Kernel 3: p = softmax_m( log(max(relu(pe·pos_w^T+pos_b),eps)) + aff )
// Logits in dynamic smem (no per-thread local arrays -> local pool stays 0).
// ---------------------------------------------------------------------------
__global__ __launch_bounds__(256, 2)
void softmax_kernel(const float* __restrict__ pe,
                    const float* __restrict__ pos_w,
                    const float* __restrict__ pos_b)
{
    extern __shared__ float sm[];
    float* pwS   = sm;            // 1024
    float* pbS   = sm + 1024;     // 16
    float* logit = sm + 1056;     // 16*1024

    const int tid = threadIdx.x;
    const int n = blockIdx.x;
    const int b = blockIdx.y;

    for (int i = tid; i < 1024; i += 256) pwS[i] = pos_w[i];
    if (tid < 16) pbS[tid] = pos_b[tid];
    __syncthreads();

    const float4* pw4 = (const float4*)pwS;
    const size_t pe_base = ((size_t)b * 1024 + n) * 65536;
    const size_t aff_row = (size_t)(b * 16) * 1048576 + (size_t)n * 1024;

#pragma unroll
    for (int i = 0; i < 4; i++) {
        const int m = tid + (i << 8);
        const float4* p4 = (const float4*)(pe + pe_base + (size_t)m * 64);
        float s[16];
#pragma unroll
        for (int g = 0; g < 16; g++) s[g] = pbS[g];
#pragma unroll
        for (int c = 0; c < 16; c++) {
            const float4 e = p4[c];
#pragma unroll
            for (int g = 0; g < 16; g++) {
                const float4 wv = pw4[g * 16 + c];
                s[g] += e.x * wv.x + e.y * wv.y + e.z * wv.z + e.w * wv.w;
            }
        }
#pragma unroll
        for (int g = 0; g < 16; g++) {
            float x = (s[g] > 1e-6f) ? __logf(s[g]) : -13.815510557964274f;
            x += g_p[aff_row + (size_t)g * 1048576 + m];
            logit[g * 1024 + m] = x;
        }
    }
    __syncthreads();

    const int lane = tid & 31;
    const int wrp  = tid >> 5;
#pragma unroll
    for (int gi = 0; gi < 2; gi++) {
        const int g = wrp * 2 + gi;
        const float* lg = logit + g * 1024;
        float l[32];
        float mx = -1e30f;
#pragma unroll
        for (int k = 0; k < 32; k++) {
            l[k] = lg[lane + (k << 5)];
            mx = fmaxf(mx, l[k]);
        }
#pragma unroll
        for (int o = 16; o > 0; o >>= 1) mx = fmaxf(mx, __shfl_xor_sync(0xffffffffu, mx, o));
        float t = 0.f;
#pragma unroll
        for (int k = 0; k < 32; k++) { l[k] = __expf(l[k] - mx); t += l[k]; }
#pragma unroll
        for (int o = 16; o > 0; o >>= 1) t += __shfl_xor_sync(0xffffffffu, t, o);
        const float inv = 1.f / t;
        float* pr = g_p + aff_row + (size_t)g * 1048576;
#pragma unroll
        for (int k = 0; k < 32; k++) pr[lane + (k << 5)] = l[k] * inv;
    }
}

// ---------------------------------------------------------------------------
// Kernel 4 (tf32 mma): out[b,n,g*64+o] = sum_m p[b,g,n,m]*V[b,m,g*64+o]+cb
// Per (b,g): C(1024n x 64o) = P(1024x1024) @ V(1024x64). Block tile 128n x
// 64o, 8 warps (4n x 2o), warp tile 32x32, K-chunk 32 over m. V transposed
// into smem as Vt[o][m] so B fragments are col-major (row.col mma).
// ---------------------------------------------------------------------------
__global__ __launch_bounds__(256, 2)
void out_mma_kernel(float* __restrict__ out, const float* __restrict__ cb)
{
    __shared__ uint32_t Ps[128][36];
    __shared__ uint32_t Vt[64][36];

    const int tid  = threadIdx.x;
    const int wid  = tid >> 5;
    const int lane = tid & 31;
    const int bg = blockIdx.y;
    const int b  = bg >> 4;
    const int g  = bg & 15;
    const int n0 = blockIdx.x << 7;
    const float* __restrict__ pp = g_p + (size_t)bg * 1048576;
    const float* __restrict__ vp = g_v + (size_t)b * 1048576 + g * 64;

    const int wm = (wid >> 1) * 32;   // n offset: 0/32/64/96
    const int wn = (wid & 1) * 32;    // o offset: 0/32
    const int qrow = lane >> 2;
    const int qcol = lane & 3;
    const int lrow = tid >> 3;        // P loader row 0..31
    const int lcol = (tid & 7) << 2;  // P loader m 0..28
    const int vm   = tid >> 4;        // V loader m 0..15
    const int vo   = (tid & 15) << 2; // V loader o 0..60

    float acc[2][4][4];
#pragma unroll
    for (int mi = 0; mi < 2; mi++)
#pragma unroll
        for (int ni = 0; ni < 4; ni++)
#pragma unroll
            for (int r = 0; r < 4; r++) acc[mi][ni][r] = 0.f;

    for (int mt = 0; mt < 1024; mt += 32) {
        __syncthreads();
#pragma unroll
        for (int it = 0; it < 4; it++) {
            const int r = lrow + it * 32;
            float4 pv = *(const float4*)(pp + (size_t)(n0 + r) * 1024 + mt + lcol);
            Ps[r][lcol + 0] = f2tf32(pv.x); Ps[r][lcol + 1] = f2tf32(pv.y);
            Ps[r][lcol + 2] = f2tf32(pv.z); Ps[r][lcol + 3] = f2tf32(pv.w);
        }
#pragma unroll
        for (int it = 0; it < 2; it++) {
            const int m = vm + it * 16;
            float4 vv = *(const float4*)(vp + (size_t)(mt + m) * 1024 + vo);
            Vt[vo + 0][m] = f2tf32(vv.x);
            Vt[vo + 1][m] = f2tf32(vv.y);
            Vt[vo + 2][m] = f2tf32(vv.z);
            Vt[vo + 3][m] = f2tf32(vv.w);
        }
        __syncthreads();
#pragma unroll
        for (int ks = 0; ks < 4; ks++) {
            const int kk = ks * 8;
            uint32_t af[2][4];
#pragma unroll
            for (int mi = 0; mi < 2; mi++) {
                const int r = wm + mi * 16;
                af[mi][0] = Ps[r + qrow][kk + qcol];
                af[mi][1] = Ps[r + 8 + qrow][kk + qcol];
                af[mi][2] = Ps[r + qrow][kk + 4 + qcol];
                af[mi][3] = Ps[r + 8 + qrow][kk + 4 + qcol];
            }
            uint32_t bf[4][2];
#pragma unroll
            for (int ni = 0; ni < 4; ni++) {
                const int c = wn + ni * 8;
                bf[ni][0] = Vt[c + qrow][kk + qcol];
                bf[ni][1] = Vt[c + qrow][kk + 4 + qcol];
            }
#pragma unroll
            for (int mi = 0; mi < 2; mi++)
#pragma unroll
                for (int ni = 0; ni < 4; ni++)
                    mma_tf32(acc[mi][ni], af[mi], bf[ni]);
        }
    }

#pragma unroll
    for (int mi = 0; mi < 2; mi++) {
        const int r = n0 + wm + mi * 16 + qrow;
#pragma unroll
        for (int ni = 0; ni < 4; ni++) {
            const int c = wn + ni * 8 + qcol * 2;   // o within group
            const float b0 = cb[g * 64 + c];
            const float b1 = cb[g * 64 + c + 1];
            float2 o0, o1;
            o0.x = acc[mi][ni][0] + b0; o0.y = acc[mi][ni][1] + b1;
            o1.x = acc[mi][ni][2] + b0; o1.y = acc[mi][ni][3] + b1;
            *(float2*)(out + ((size_t)(b * 1024 + r)) * 1024 + g * 64 + c)       = o0;
            *(float2*)(out + ((size_t)(b * 1024 + r + 8)) * 1024 + g * 64 + c)   = o1;
        }
    }
}

static const int kSoftmaxSmem = (1056 + 16 * 1024) * 4;   // 69,760 bytes

// ---------------------------------------------------------------------------
extern "C" void kernel_launch(void* const* d_in, const int* in_sizes, int n_in,
                              void* d_out, int out_size)
{
    (void)in_sizes; (void)n_in; (void)out_size;
    const float* roi   = (const float*)d_in[0];
    const float* pe    = (const float*)d_in[1];
    const float* pos_w = (const float*)d_in[2];
    const float* pos_b = (const float*)d_in[3];
    const float* q_w   = (const float*)d_in[4];
    const float* q_b   = (const float*)d_in[5];
    const float* k_w   = (const float*)d_in[6];
    const float* k_b   = (const float*)d_in[7];
    const float* c_w   = (const float*)d_in[8];
    const float* c_b   = (const float*)d_in[9];
    float* out = (float*)d_out;

    cudaFuncSetAttribute(softmax_kernel,
                         cudaFuncAttributeMaxDynamicSharedMemorySize, kSoftmaxSmem);

    proj_mma_kernel<<<dim3(24, 16), 256>>>(roi, q_w, q_b, k_w, k_b, c_w);
    aff_mma_kernel<<<dim3(8, 8, 32), 256>>>();
    softmax_kernel<<<dim3(1024, 2), 256, kSoftmaxSmem>>>(pe, pos_w, pos_b);
    out_mma_kernel<<<dim3(8, 32), 256>>>(out, c_b);
}